// round 10
// baseline (speedup 1.0000x reference)
#include <cuda_runtime.h>
#include <cstdint>

// NonLocalMeansSmoothing: x [8,256,256,8] fp32 -> same. K=5, sigma=1, h=1.
// w ∝ exp(-(||c-n||^2 + 0.5*(di^2+dj^2)))  (gaussian global norm cancels)
// ||c-n||^2 = ||c||^2 + ||n||^2 - 2 c·n, norms pre-scaled by -log2e in smem.
//
// R10: ONE 1024-thread CTA per SM (R1's high-issue config), 32x32 tile,
// 1 pixel/thread, STATIC 47KB smem (no attribute calls), R3-grade packed
// f32x2 math + tree-shaped dot + precomputed pc+cg table (6 values).

#define BATCH 8
#define NX 256
#define NY 256
#define TILE 32
#define HALO 2
#define SMW (TILE + 2 * HALO)   // 36
#define L2E 1.4426950408889634f

typedef unsigned long long u64;

__device__ __forceinline__ u64 fma2(u64 a, u64 b, u64 c) {
    u64 d; asm("fma.rn.f32x2 %0,%1,%2,%3;" : "=l"(d) : "l"(a), "l"(b), "l"(c)); return d;
}
__device__ __forceinline__ u64 mul2(u64 a, u64 b) {
    u64 d; asm("mul.rn.f32x2 %0,%1,%2;" : "=l"(d) : "l"(a), "l"(b)); return d;
}
__device__ __forceinline__ u64 add2(u64 a, u64 b) {
    u64 d; asm("add.rn.f32x2 %0,%1,%2;" : "=l"(d) : "l"(a), "l"(b)); return d;
}
__device__ __forceinline__ u64 pack2(float lo, float hi) {
    u64 d; asm("mov.b64 %0,{%1,%2};" : "=l"(d) : "f"(lo), "f"(hi)); return d;
}
__device__ __forceinline__ float hadd2(u64 a) {
    float lo, hi; asm("mov.b64 {%0,%1},%2;" : "=f"(lo), "=f"(hi) : "l"(a));
    return lo + hi;
}
__device__ __forceinline__ float ex2f(float x) {
    float r; asm("ex2.approx.ftz.f32 %0,%1;" : "=f"(r) : "f"(x)); return r;
}
__device__ __forceinline__ int refl(int p, int n) {
    if (p < 0) p = -p;
    if (p >= n) p = 2 * n - 2 - p;
    return p;
}

// index into pcg[] for s = di*di + dj*dj ∈ {0,1,2,4,5,8}
__device__ __forceinline__ constexpr int sidx(int s) {
    return (s == 0) ? 0 : (s == 1) ? 1 : (s == 2) ? 2
         : (s == 4) ? 3 : (s == 5) ? 4 : 5;
}

__global__ __launch_bounds__(1024, 1)
void nlm_kernel(const float* __restrict__ x, float* __restrict__ out) {
    __shared__ ulonglong2 sm0[SMW][SMW];   // ch 0-3
    __shared__ ulonglong2 sm1[SMW][SMW];   // ch 4-7
    __shared__ float      snl[SMW][SMW];   // -log2e * ||v||^2

    const int b   = blockIdx.z;
    const int ti0 = blockIdx.y * TILE;
    const int tj0 = blockIdx.x * TILE;
    const int tid = threadIdx.y * 32 + threadIdx.x;

    const float* xb = x + (size_t)b * NX * NY * 8;

    // Halo load: 1296 sites / 1024 threads.
    for (int p = tid; p < SMW * SMW; p += 1024) {
        int r = p / SMW;
        int c = p - r * SMW;
        int gi = refl(ti0 + r - HALO, NX);
        int gj = refl(tj0 + c - HALO, NY);
        const float4* src = reinterpret_cast<const float4*>(
            xb + ((size_t)gi * NY + gj) * 8);
        float4 v0 = src[0];
        float4 v1 = src[1];
        *reinterpret_cast<float4*>(&sm0[r][c]) = v0;
        *reinterpret_cast<float4*>(&sm1[r][c]) = v1;
        float nrm = v0.x * v0.x + v0.y * v0.y + v0.z * v0.z + v0.w * v0.w
                  + v1.x * v1.x + v1.y * v1.y + v1.z * v1.z + v1.w * v1.w;
        snl[r][c] = -L2E * nrm;
    }
    __syncthreads();

    const int li = threadIdx.y + HALO;
    const int lj = threadIdx.x + HALO;

    const ulonglong2 C0 = sm0[li][lj];
    const ulonglong2 C1 = sm1[li][lj];
    const float pc = snl[li][lj];           // -log2e*||c||^2

    // pc + cg for the 6 distinct di^2+dj^2 values {0,1,2,4,5,8}
    float pcg[6];
    pcg[0] = pc;
    pcg[1] = pc - L2E * 0.5f;
    pcg[2] = pc - L2E * 1.0f;
    pcg[3] = pc - L2E * 2.0f;
    pcg[4] = pc - L2E * 2.5f;
    pcg[5] = pc - L2E * 4.0f;

    u64 a0 = 0, a1 = 0, a2 = 0, a3 = 0;
    float wsum = 0.f;

#pragma unroll
    for (int di = -HALO; di <= HALO; di++) {
#pragma unroll
        for (int dj = -HALO; dj <= HALO; dj++) {
            const ulonglong2 N0 = sm0[li + di][lj + dj];
            const ulonglong2 N1 = sm1[li + di][lj + dj];
            const float ns = snl[li + di][lj + dj];

            // tree-shaped 8-channel dot
            u64 dp1 = mul2(C0.x, N0.x);
            u64 dp2 = mul2(C0.y, N0.y);
            dp1 = fma2(C1.x, N1.x, dp1);
            dp2 = fma2(C1.y, N1.y, dp2);
            const float dot = hadd2(add2(dp1, dp2));

            const int s = di * di + dj * dj;
            const float e = fmaf(2.0f * L2E, dot, pcg[sidx(s)] + ns);
            const float w = ex2f(e);
            const u64 w2 = pack2(w, w);
            a0 = fma2(w2, N0.x, a0);
            a1 = fma2(w2, N0.y, a1);
            a2 = fma2(w2, N1.x, a2);
            a3 = fma2(w2, N1.y, a3);
            wsum += w;
        }
    }

    const float inv = __fdividef(1.f, wsum);
    const u64 inv2 = pack2(inv, inv);
    ulonglong2 r0, r1;
    r0.x = mul2(a0, inv2); r0.y = mul2(a1, inv2);
    r1.x = mul2(a2, inv2); r1.y = mul2(a3, inv2);

    const int gi = ti0 + threadIdx.y;
    const int gj = tj0 + threadIdx.x;
    ulonglong2* dst = reinterpret_cast<ulonglong2*>(
        out + (((size_t)b * NX + gi) * NY + gj) * 8);
    dst[0] = r0;
    dst[1] = r1;
}

extern "C" void kernel_launch(void* const* d_in, const int* in_sizes, int n_in,
                              void* d_out, int out_size) {
    const float* x = (const float*)d_in[0];
    float* out = (float*)d_out;
    dim3 block(32, 32, 1);
    dim3 grid(NY / TILE, NX / TILE, BATCH);  // (8, 8, 8) = 512 CTAs
    nlm_kernel<<<grid, block>>>(x, out);
}

// round 11
// speedup vs baseline: 1.2611x; 1.2611x over previous
#include <cuda_runtime.h>
#include <cstdint>

// NonLocalMeansSmoothing: x [8,256,256,8] fp32 -> same. K=5, sigma=1, h=1.
// w ∝ exp(-(||c-n||^2 + 0.5*(di^2+dj^2)))  (gaussian global norm cancels)
// ||c-n||^2 = ||c||^2 + ||n||^2 - 2 c·n, norms pre-scaled by -log2e in smem.
//
// R11: occupancy play. 1 px/thread with a deliberately lean register
// footprint; __launch_bounds__(512, 3) caps regs at 40 -> 48 warps/SM
// (vs 32 in every prior round). Trades per-thread ILP + load sharing for
// +50% TLP against the latency-exposure bottleneck.

#define BATCH 8
#define NX 256
#define NY 256
#define TILEX 32            // columns (ny)
#define TILEY 16            // rows (nx)
#define HALO 2
#define SMX (TILEX + 2 * HALO)   // 36
#define SMY (TILEY + 2 * HALO)   // 20
#define L2E 1.4426950408889634f

typedef unsigned long long u64;

__device__ __forceinline__ u64 fma2(u64 a, u64 b, u64 c) {
    u64 d; asm("fma.rn.f32x2 %0,%1,%2,%3;" : "=l"(d) : "l"(a), "l"(b), "l"(c)); return d;
}
__device__ __forceinline__ u64 mul2(u64 a, u64 b) {
    u64 d; asm("mul.rn.f32x2 %0,%1,%2;" : "=l"(d) : "l"(a), "l"(b)); return d;
}
__device__ __forceinline__ u64 add2(u64 a, u64 b) {
    u64 d; asm("add.rn.f32x2 %0,%1,%2;" : "=l"(d) : "l"(a), "l"(b)); return d;
}
__device__ __forceinline__ u64 pack2(float lo, float hi) {
    u64 d; asm("mov.b64 %0,{%1,%2};" : "=l"(d) : "f"(lo), "f"(hi)); return d;
}
__device__ __forceinline__ float hadd2(u64 a) {
    float lo, hi; asm("mov.b64 {%0,%1},%2;" : "=f"(lo), "=f"(hi) : "l"(a));
    return lo + hi;
}
__device__ __forceinline__ float ex2f(float x) {
    float r; asm("ex2.approx.ftz.f32 %0,%1;" : "=f"(r) : "f"(x)); return r;
}
__device__ __forceinline__ int refl(int p, int n) {
    if (p < 0) p = -p;
    if (p >= n) p = 2 * n - 2 - p;
    return p;
}

__global__ __launch_bounds__(512, 3)
void nlm_kernel(const float* __restrict__ x, float* __restrict__ out) {
    __shared__ ulonglong2 sm0[SMY][SMX];   // ch 0-3
    __shared__ ulonglong2 sm1[SMY][SMX];   // ch 4-7
    __shared__ float      snl[SMY][SMX];   // -log2e * ||v||^2

    const int b   = blockIdx.z;
    const int ti0 = blockIdx.y * TILEY;
    const int tj0 = blockIdx.x * TILEX;
    const int tid = threadIdx.y * 32 + threadIdx.x;

    const float* xb = x + (size_t)b * NX * NY * 8;

    // Halo load: 720 sites / 512 threads.
    for (int p = tid; p < SMY * SMX; p += 512) {
        int r = p / SMX;
        int c = p - r * SMX;
        int gi = refl(ti0 + r - HALO, NX);
        int gj = refl(tj0 + c - HALO, NY);
        const float4* src = reinterpret_cast<const float4*>(
            xb + ((size_t)gi * NY + gj) * 8);
        float4 v0 = src[0];
        float4 v1 = src[1];
        *reinterpret_cast<float4*>(&sm0[r][c]) = v0;
        *reinterpret_cast<float4*>(&sm1[r][c]) = v1;
        float nrm = v0.x * v0.x + v0.y * v0.y + v0.z * v0.z + v0.w * v0.w
                  + v1.x * v1.x + v1.y * v1.y + v1.z * v1.z + v1.w * v1.w;
        snl[r][c] = -L2E * nrm;
    }
    __syncthreads();

    const int li = threadIdx.y + HALO;
    const int lj = threadIdx.x + HALO;

    const ulonglong2 C0 = sm0[li][lj];
    const ulonglong2 C1 = sm1[li][lj];
    const float pc = snl[li][lj];           // -log2e*||c||^2

    u64 a0 = 0, a1 = 0, a2 = 0, a3 = 0;
    float wsum = 0.f;

#pragma unroll
    for (int di = -HALO; di <= HALO; di++) {
#pragma unroll
        for (int dj = -HALO; dj <= HALO; dj++) {
            const ulonglong2 N0 = sm0[li + di][lj + dj];
            const ulonglong2 N1 = sm1[li + di][lj + dj];
            const float ns = snl[li + di][lj + dj];

            // tree-shaped 8-channel dot
            u64 dp1 = mul2(C0.x, N0.x);
            u64 dp2 = mul2(C0.y, N0.y);
            dp1 = fma2(C1.x, N1.x, dp1);
            dp2 = fma2(C1.y, N1.y, dp2);
            const float dot = hadd2(add2(dp1, dp2));

            const float cg = -L2E * (0.5f * (float)(di * di + dj * dj));
            const float e = fmaf(2.0f * L2E, dot, (ns + cg) + pc);
            const float w = ex2f(e);
            const u64 w2 = pack2(w, w);
            a0 = fma2(w2, N0.x, a0);
            a1 = fma2(w2, N0.y, a1);
            a2 = fma2(w2, N1.x, a2);
            a3 = fma2(w2, N1.y, a3);
            wsum += w;
        }
    }

    const float inv = __fdividef(1.f, wsum);
    const u64 inv2 = pack2(inv, inv);
    ulonglong2 r0, r1;
    r0.x = mul2(a0, inv2); r0.y = mul2(a1, inv2);
    r1.x = mul2(a2, inv2); r1.y = mul2(a3, inv2);

    const int gi = ti0 + threadIdx.y;
    const int gj = tj0 + threadIdx.x;
    ulonglong2* dst = reinterpret_cast<ulonglong2*>(
        out + (((size_t)b * NX + gi) * NY + gj) * 8);
    dst[0] = r0;
    dst[1] = r1;
}

extern "C" void kernel_launch(void* const* d_in, const int* in_sizes, int n_in,
                              void* d_out, int out_size) {
    const float* x = (const float*)d_in[0];
    float* out = (float*)d_out;
    dim3 block(32, 16, 1);
    dim3 grid(NY / TILEX, NX / TILEY, BATCH);  // (8, 16, 8) = 1024 CTAs
    nlm_kernel<<<grid, block>>>(x, out);
}